// round 10
// baseline (speedup 1.0000x reference)
#include <cuda_runtime.h>
#include <cuda_fp16.h>
#include <cstdint>

#define Dm 2048
#define Bm 256

// scratch (no cudaMalloc allowed)
__device__ float g_bcx[Bm * 3 * Dm];                 // GEMM1 out [256, 6144] fp32
__device__ __align__(16) __half g_w1h[3 * Dm * Dm];  // w1 fp16 [6144, 2048]
__device__ __align__(16) __half g_w2h[Dm * Dm];      // w2 fp16 [2048, 2048]
__device__ __align__(16) __half g_xh[Bm * Dm];       // x  fp16 [256, 2048]
__device__ __align__(16) __half g_yh[Bm * Dm];       // y  fp16 [256, 2048]

__device__ __forceinline__ uint32_t pack_h2(float lo, float hi) {
    uint32_t r;
    asm("cvt.rn.f16x2.f32 %0, %1, %2;" : "=r"(r) : "f"(hi), "f"(lo));
    return r;
}

__device__ __forceinline__ void mma16(float* d, const uint32_t* a, const uint32_t* b) {
    asm volatile(
        "mma.sync.aligned.m16n8k16.row.col.f32.f16.f16.f32 "
        "{%0,%1,%2,%3}, {%4,%5,%6,%7}, {%8,%9}, {%0,%1,%2,%3};"
        : "+f"(d[0]), "+f"(d[1]), "+f"(d[2]), "+f"(d[3])
        : "r"(a[0]), "r"(a[1]), "r"(a[2]), "r"(a[3]), "r"(b[0]), "r"(b[1]));
}

__device__ __forceinline__ void ldsm4(uint32_t* r, uint32_t addr) {
    asm volatile("ldmatrix.sync.aligned.m8n8.x4.shared.b16 {%0,%1,%2,%3}, [%4];"
                 : "=r"(r[0]), "=r"(r[1]), "=r"(r[2]), "=r"(r[3]) : "r"(addr));
}
__device__ __forceinline__ void cp16(uint32_t saddr, const void* gptr) {
    asm volatile("cp.async.cg.shared.global [%0], [%1], 16;"
                 :: "r"(saddr), "l"(gptr));
}
#define CP_COMMIT() asm volatile("cp.async.commit_group;" ::: "memory")
#define CP_WAIT(n)  asm volatile("cp.async.wait_group %0;" :: "n"(n) : "memory")

// ---------------------------------------------------------------------------
// merged fp32 -> fp16 convert for w1 | w2 | x (grid-stride, HBM-bound)
// ---------------------------------------------------------------------------
__global__ __launch_bounds__(256) void k_cvt_all(
    const float4* __restrict__ w1, const float4* __restrict__ w2,
    const float4* __restrict__ x,
    uint2* __restrict__ w1h, uint2* __restrict__ w2h, uint2* __restrict__ xh)
{
    constexpr int N1 = 3 * Dm * Dm / 4;
    constexpr int N2 = Dm * Dm / 4;
    constexpr int N3 = Bm * Dm / 4;
    const int stride = gridDim.x * 256;
    for (int i = blockIdx.x * 256 + threadIdx.x; i < N1 + N2 + N3; i += stride) {
        const float4* s; uint2* d; int j;
        if (i < N1)            { s = w1; d = w1h; j = i; }
        else if (i < N1 + N2)  { s = w2; d = w2h; j = i - N1; }
        else                   { s = x;  d = xh;  j = i - N1 - N2; }
        float4 v = s[j];
        d[j] = make_uint2(pack_h2(v.x, v.y), pack_h2(v.z, v.w));
    }
}

// ---------------------------------------------------------------------------
// fp16 tensor-core GEMM, cp.async multi-stage: C[M,N] = A[M,K] @ Bw[N,K]^T
// PITCH = BK*2+16 -> all ldmatrix 8-row phases hit distinct 16B bank-quads.
// A and B fragments both via ldmatrix.x4 (B covers n16 x k16 per x4).
// ---------------------------------------------------------------------------
template <int BM, int BN, int BK, int WM, int WN, int THREADS, int STAGES,
          int MINCTA>
__global__ __launch_bounds__(THREADS, MINCTA) void k_mma_f16cp(
    const __half* __restrict__ A, const __half* __restrict__ Bw,
    float* __restrict__ C, int lda, int ldb, int ldc)
{
    extern __shared__ uint8_t smem[];
    constexpr int ROWS = BM + BN;
    constexpr int PITCH = BK * 2 + 16;
    constexpr int STGB = ROWS * PITCH;
    constexpr int MT = WM / 16, NT = WN / 8;
    constexpr int NP = NT / 2;                // B ldmatrix.x4 pairs (n16 each)
    constexpr int WARPS_N = BN / WN;
    constexpr int RCH = BK * 2 / 16;
    constexpr int NCHUNK = ROWS * RCH / THREADS;
    constexpr int NSTG = Dm / BK;
    constexpr int KSTEPS = BK / 16;

    const int tid = threadIdx.x;
    const int wid = tid >> 5, lane = tid & 31;
    const int g = lane >> 2, c = lane & 3;
    const int wm = (wid / WARPS_N) * WM, wn = (wid % WARPS_N) * WN;
    const int mBase = blockIdx.y * BM, nBase = blockIdx.x * BN;

    const uint32_t sbase = (uint32_t)__cvta_generic_to_shared(smem);

    const int lr = lane & 7, mat = lane >> 3;
    // A x4: matrices {rows0-7 klo, rows8-15 klo, rows0-7 khi, rows8-15 khi}
    uint32_t aoff[MT];
    #pragma unroll
    for (int mt = 0; mt < MT; mt++)
        aoff[mt] = (uint32_t)(wm + mt * 16 + lr + (mat & 1) * 8) * PITCH
                 + (uint32_t)(mat >> 1) * 16;
    // B x4: matrices {n0-7 klo, n0-7 khi, n8-15 klo, n8-15 khi}
    uint32_t boff[NP];
    #pragma unroll
    for (int p = 0; p < NP; p++)
        boff[p] = (uint32_t)(BM + wn + p * 16 + (mat >> 1) * 8 + lr) * PITCH
                + (uint32_t)(mat & 1) * 16;

    float acc[MT][NT][4] = {};

    auto load_stage = [&](int s, int k0) {   // k0 in halves
        #pragma unroll
        for (int i = 0; i < NCHUNK; i++) {
            int idx = tid + i * THREADS;
            int row = idx / RCH, ch = idx % RCH;
            const __half* gptr = (row < BM)
                ? &A[(size_t)(mBase + row) * lda + k0 + ch * 8]
                : &Bw[(size_t)(nBase + row - BM) * ldb + k0 + ch * 8];
            cp16(sbase + s * STGB + (uint32_t)row * PITCH + ch * 16, gptr);
        }
    };

    #pragma unroll
    for (int s = 0; s < STAGES - 1; s++) { load_stage(s, s * BK); CP_COMMIT(); }

    for (int s = 0; s < NSTG; s++) {
        CP_WAIT(STAGES - 2);
        __syncthreads();

        const int nxt = s + STAGES - 1;
        if (nxt < NSTG) load_stage(nxt % STAGES, nxt * BK);
        CP_COMMIT();

        const uint32_t sb = sbase + (s % STAGES) * STGB;
        #pragma unroll
        for (int step = 0; step < KSTEPS; step++) {
            const uint32_t kb = step * 32;
            uint32_t af[MT][4], bf[NT][2];
            #pragma unroll
            for (int mt = 0; mt < MT; mt++)
                ldsm4(af[mt], sb + aoff[mt] + kb);
            #pragma unroll
            for (int p = 0; p < NP; p++) {
                uint32_t r[4];
                ldsm4(r, sb + boff[p] + kb);
                bf[2 * p][0] = r[0]; bf[2 * p][1] = r[1];
                bf[2 * p + 1][0] = r[2]; bf[2 * p + 1][1] = r[3];
            }
            #pragma unroll
            for (int mt = 0; mt < MT; mt++)
                #pragma unroll
                for (int nt = 0; nt < NT; nt++)
                    mma16(acc[mt][nt], af[mt], bf[nt]);
        }
    }

    #pragma unroll
    for (int mt = 0; mt < MT; mt++) {
        const int row = mBase + wm + mt * 16 + g;
        #pragma unroll
        for (int nt = 0; nt < NT; nt++) {
            const int col = nBase + wn + nt * 8 + 2 * c;
            *reinterpret_cast<float2*>(&C[(size_t)row * ldc + col]) =
                make_float2(acc[mt][nt][0], acc[mt][nt][1]);
            *reinterpret_cast<float2*>(&C[(size_t)(row + 8) * ldc + col]) =
                make_float2(acc[mt][nt][2], acc[mt][nt][3]);
        }
    }
}

// ---------------------------------------------------------------------------
// Elementwise: gates + cache roll/scatter + depthwise conv + C-gate.
// Emits y as fp16 for GEMM2.
// ---------------------------------------------------------------------------
__global__ __launch_bounds__(256) void k_elem(
    const float* __restrict__ conv_cache, const float* __restrict__ conv_w,
    const int* __restrict__ pos_ids, float* __restrict__ out_state)
{
    const int idx = blockIdx.x * 256 + threadIdx.x;   // b*2048 + d
    const int b = idx >> 11, d = idx & 2047;

    const float Bg = g_bcx[(size_t)b * 6144 + d];
    const float Cg = g_bcx[(size_t)b * 6144 + 2048 + d];
    const float xg = g_bcx[(size_t)b * 6144 + 4096 + d];
    const float Bx = Bg * xg;

    int pos = pos_ids[0];
    pos = min(max(pos, 0), 3);

    const float4 cc = *reinterpret_cast<const float4*>(conv_cache + (size_t)idx * 4);
    float st[4] = {cc.y, cc.z, cc.w, cc.x};   // roll left by 1
    st[pos] = Bx;

    const float4 cw = *reinterpret_cast<const float4*>(conv_w + (size_t)d * 4);
    const float co = st[0] * cw.x + st[1] * cw.y + st[2] * cw.z + st[3] * cw.w;

    g_yh[idx] = __float2half(Cg * co);
    *reinterpret_cast<float4*>(out_state + (size_t)idx * 4) =
        make_float4(st[0], st[1], st[2], st[3]);
}

// ---------------------------------------------------------------------------
extern "C" void kernel_launch(void* const* d_in, const int* in_sizes, int n_in,
                              void* d_out, int out_size) {
    const float* x          = (const float*)d_in[0];
    const float* conv_cache = (const float*)d_in[1];
    const float* w1         = (const float*)d_in[2];
    const float* w2         = (const float*)d_in[3];
    const float* conv_w     = (const float*)d_in[4];
    const int*   pos_ids    = (const int*)d_in[5];

    float* out       = (float*)d_out;            // [B,1,D]
    float* out_state = out + (size_t)Bm * Dm;    // [B,D,K]

    float* bcx = nullptr;
    __half *w1h = nullptr, *w2h = nullptr, *xh = nullptr, *yh = nullptr;
    cudaGetSymbolAddress((void**)&bcx, g_bcx);
    cudaGetSymbolAddress((void**)&w1h, g_w1h);
    cudaGetSymbolAddress((void**)&w2h, g_w2h);
    cudaGetSymbolAddress((void**)&xh, g_xh);
    cudaGetSymbolAddress((void**)&yh, g_yh);

    // merged fp32 -> fp16 converts
    k_cvt_all<<<2048, 256>>>((const float4*)w1, (const float4*)w2,
                             (const float4*)x,
                             (uint2*)w1h, (uint2*)w2h, (uint2*)xh);

    // GEMM1: 64x96 tile, BK=64, 2 warps (64x48), 4 stages, 2 CTAs/SM
    // smem = 4 * 160 * 144 = 92160 B; grid = 64 x 4 = 256 CTAs
    constexpr int SMEM1 = 4 * (64 + 96) * 144;
    // GEMM2: 64x64 tile, BK=64, 4 warps (32x32), 5 stages
    // smem = 5 * 128 * 144 = 92160 B; grid = 32 x 4 = 128 CTAs
    constexpr int SMEM2 = 5 * (64 + 64) * 144;
    cudaFuncSetAttribute((const void*)k_mma_f16cp<64, 96, 64, 64, 48, 64, 4, 2>,
                         cudaFuncAttributeMaxDynamicSharedMemorySize, SMEM1);
    cudaFuncSetAttribute((const void*)k_mma_f16cp<64, 64, 64, 32, 32, 128, 5, 1>,
                         cudaFuncAttributeMaxDynamicSharedMemorySize, SMEM2);

    // GEMM1: BCx[256, 6144] = x[256,2048] @ w1[6144,2048]^T
    k_mma_f16cp<64, 96, 64, 64, 48, 64, 4, 2>
        <<<dim3(3 * Dm / 96, Bm / 64), 64, SMEM1>>>(xh, w1h, bcx, Dm, Dm, 3 * Dm);

    // gating + conv + state scatter
    k_elem<<<(Bm * Dm) / 256, 256>>>(conv_cache, conv_w, pos_ids, out_state);

    // GEMM2: out[256, 2048] = y[256,2048] @ w2[2048,2048]^T
    k_mma_f16cp<64, 64, 64, 32, 32, 128, 5, 1>
        <<<dim3(Dm / 64, Bm / 64), 128, SMEM2>>>(yh, w2h, out, Dm, Dm, Dm);
}

// round 11
// speedup vs baseline: 1.1896x; 1.1896x over previous
#include <cuda_runtime.h>
#include <cuda_fp16.h>
#include <cuda.h>
#include <cstdint>

#define Dm 2048
#define Bm 256

// scratch (no cudaMalloc allowed)
__device__ float g_bcx[Bm * 3 * Dm];                 // GEMM1 out [256, 6144] fp32
__device__ __align__(16) __half g_w1h[3 * Dm * Dm];  // w1 fp16 [6144, 2048]
__device__ __align__(16) __half g_w2h[Dm * Dm];      // w2 fp16 [2048, 2048]
__device__ __align__(16) __half g_xh[Bm * Dm];       // x  fp16 [256, 2048]
__device__ __align__(16) __half g_yh[Bm * Dm];       // y  fp16 [256, 2048]
__device__ __align__(16) float  g_p[2 * Bm * Dm];    // GEMM2 split-K partials

__device__ __forceinline__ uint32_t pack_h2(float lo, float hi) {
    uint32_t r;
    asm("cvt.rn.f16x2.f32 %0, %1, %2;" : "=r"(r) : "f"(hi), "f"(lo));
    return r;
}
__device__ __forceinline__ void mma16(float* d, const uint32_t* a, const uint32_t* b) {
    asm volatile(
        "mma.sync.aligned.m16n8k16.row.col.f32.f16.f16.f32 "
        "{%0,%1,%2,%3}, {%4,%5,%6,%7}, {%8,%9}, {%0,%1,%2,%3};"
        : "+f"(d[0]), "+f"(d[1]), "+f"(d[2]), "+f"(d[3])
        : "r"(a[0]), "r"(a[1]), "r"(a[2]), "r"(a[3]), "r"(b[0]), "r"(b[1]));
}
__device__ __forceinline__ void ldsm4(uint32_t* r, uint32_t addr) {
    asm volatile("ldmatrix.sync.aligned.m8n8.x4.shared.b16 {%0,%1,%2,%3}, [%4];"
                 : "=r"(r[0]), "=r"(r[1]), "=r"(r[2]), "=r"(r[3]) : "r"(addr));
}
__device__ __forceinline__ void mbar_init(uint32_t addr, uint32_t cnt) {
    asm volatile("mbarrier.init.shared.b64 [%0], %1;" :: "r"(addr), "r"(cnt) : "memory");
}
__device__ __forceinline__ void mbar_expect_tx(uint32_t addr, uint32_t bytes) {
    asm volatile("mbarrier.arrive.expect_tx.shared.b64 _, [%0], %1;"
                 :: "r"(addr), "r"(bytes) : "memory");
}
__device__ __forceinline__ void mbar_wait(uint32_t addr, uint32_t parity) {
    asm volatile(
        "{\n\t.reg .pred P1;\n\t"
        "WL%=:\n\t"
        "mbarrier.try_wait.parity.shared.b64 P1, [%0], %1;\n\t"
        "@P1 bra.uni WD%=;\n\t"
        "bra.uni WL%=;\n\t"
        "WD%=:\n\t}"
        :: "r"(addr), "r"(parity) : "memory");
}
__device__ __forceinline__ void tma2d(uint32_t saddr, const void* tm,
                                      int32_t x, int32_t y, uint32_t mbar) {
    asm volatile(
        "cp.async.bulk.tensor.2d.shared::cta.global.tile.mbarrier::complete_tx::bytes "
        "[%0], [%1, {%2, %3}], [%4];"
        :: "r"(saddr), "l"(tm), "r"(x), "r"(y), "r"(mbar) : "memory");
}

// ---------------------------------------------------------------------------
// merged fp32 -> fp16 convert for w1 | w2 | x (grid-stride, HBM-bound)
// ---------------------------------------------------------------------------
__global__ __launch_bounds__(256) void k_cvt_all(
    const float4* __restrict__ w1, const float4* __restrict__ w2,
    const float4* __restrict__ x,
    uint2* __restrict__ w1h, uint2* __restrict__ w2h, uint2* __restrict__ xh)
{
    constexpr int N1 = 3 * Dm * Dm / 4;
    constexpr int N2 = Dm * Dm / 4;
    constexpr int N3 = Bm * Dm / 4;
    const int stride = gridDim.x * 256;
    for (int i = blockIdx.x * 256 + threadIdx.x; i < N1 + N2 + N3; i += stride) {
        const float4* s; uint2* d; int j;
        if (i < N1)            { s = w1; d = w1h; j = i; }
        else if (i < N1 + N2)  { s = w2; d = w2h; j = i - N1; }
        else                   { s = x;  d = xh;  j = i - N1 - N2; }
        float4 v = s[j];
        d[j] = make_uint2(pack_h2(v.x, v.y), pack_h2(v.z, v.w));
    }
}

// ---------------------------------------------------------------------------
// fp16 tensor-core GEMM, TMA + mbarrier pipeline: C[M,N] = A[M,K] @ Bw[N,K]^T
// SW128-swizzled smem tiles (128B rows of BK=64 halves); ldmatrix with XOR
// swizzle. PART: write to split-K partial buffer at row offset z*Bm.
// ---------------------------------------------------------------------------
template <int BM, int BN, int WM, int WN, int STAGES, int SPLITK, bool PART>
__global__ __launch_bounds__(128, 1) void k_tma(
    const __grid_constant__ CUtensorMap tmA,
    const __grid_constant__ CUtensorMap tmB,
    float* __restrict__ C, int ldc)
{
    extern __shared__ uint8_t smem[];
    constexpr int BK = 64;                       // 64 halves = 128B rows
    constexpr int ROWS = BM + BN;
    constexpr int STGB = ROWS * 128;             // multiple of 1024
    constexpr int MT = WM / 16, NT = WN / 8, NP = NT / 2;
    constexpr int WARPS_N = BN / WN;
    constexpr int KLEN = Dm / SPLITK;
    constexpr int NSTG = KLEN / BK;
    constexpr int KSTEPS = BK / 16;

    const int tid = threadIdx.x;
    const int wid = tid >> 5, lane = tid & 31;
    const int g = lane >> 2, c = lane & 3;
    const int wm = (wid / WARPS_N) * WM, wn = (wid % WARPS_N) * WN;
    const int mBase = blockIdx.y * BM, nBase = blockIdx.x * BN;
    const int kBase = PART ? blockIdx.z * KLEN : 0;

    uint32_t sraw = (uint32_t)__cvta_generic_to_shared(smem);
    const uint32_t mb0 = sraw;                        // STAGES mbarriers (8B each)
    const uint32_t sb0 = (sraw + 1023u) & ~1023u;     // 1KB-aligned tile region
    const uint32_t sbA = (sb0 < sraw + 8u * STAGES) ? sb0 + 1024u : sb0;

    if (tid == 0)
        for (int i = 0; i < STAGES; i++) mbar_init(mb0 + i * 8, 1);
    __syncthreads();

    // per-lane ldmatrix geometry (XOR swizzle: chunk ^ (lr<<4))
    const int lr = lane & 7, mat = lane >> 3;
    const uint32_t axor = (uint32_t)lr << 4;
    uint32_t arow[MT]; const uint32_t acb = (uint32_t)(mat >> 1) * 16;
    #pragma unroll
    for (int mt = 0; mt < MT; mt++)
        arow[mt] = (uint32_t)(wm + mt * 16 + (mat & 1) * 8 + lr) * 128;
    uint32_t brow[NP]; const uint32_t bcb = (uint32_t)(mat & 1) * 16;
    #pragma unroll
    for (int p = 0; p < NP; p++)
        brow[p] = (uint32_t)(BM + wn + p * 16 + (mat >> 1) * 8 + lr) * 128;

    float acc[MT][NT][4] = {};

    auto issue = [&](int slot, int k0) {
        if (tid == 0) {
            const uint32_t bar = mb0 + slot * 8;
            mbar_expect_tx(bar, STGB);
            tma2d(sbA + slot * STGB, &tmA, k0, mBase, bar);
            tma2d(sbA + slot * STGB + BM * 128, &tmB, k0, nBase, bar);
        }
    };

    #pragma unroll
    for (int s = 0; s < STAGES - 1; s++) issue(s, kBase + s * BK);

    int slot = 0, ph = 0, islot = STAGES - 1;
    for (int s = 0; s < NSTG; s++) {
        mbar_wait(mb0 + slot * 8, ph);
        __syncthreads();                    // all warps done with previous buffer

        if (s + STAGES - 1 < NSTG) issue(islot, kBase + (s + STAGES - 1) * BK);
        islot = (islot + 1 == STAGES) ? 0 : islot + 1;

        const uint32_t sb = sbA + slot * STGB;
        #pragma unroll
        for (int step = 0; step < KSTEPS; step++) {
            const uint32_t kb = step * 32;
            uint32_t af[MT][4], bf[NT][2];
            #pragma unroll
            for (int mt = 0; mt < MT; mt++)
                ldsm4(af[mt], sb + arow[mt] + ((acb + kb) ^ axor));
            #pragma unroll
            for (int p = 0; p < NP; p++) {
                uint32_t r[4];
                ldsm4(r, sb + brow[p] + ((bcb + kb) ^ axor));
                bf[2 * p][0] = r[0]; bf[2 * p][1] = r[1];
                bf[2 * p + 1][0] = r[2]; bf[2 * p + 1][1] = r[3];
            }
            #pragma unroll
            for (int mt = 0; mt < MT; mt++)
                #pragma unroll
                for (int nt = 0; nt < NT; nt++)
                    mma16(acc[mt][nt], af[mt], bf[nt]);
        }
        slot++; if (slot == STAGES) { slot = 0; ph ^= 1; }
    }

    const int rOff = PART ? (int)blockIdx.z * Bm : 0;
    #pragma unroll
    for (int mt = 0; mt < MT; mt++) {
        const int row = rOff + mBase + wm + mt * 16 + g;
        #pragma unroll
        for (int nt = 0; nt < NT; nt++) {
            const int col = nBase + wn + nt * 8 + 2 * c;
            *reinterpret_cast<float2*>(&C[(size_t)row * ldc + col]) =
                make_float2(acc[mt][nt][0], acc[mt][nt][1]);
            *reinterpret_cast<float2*>(&C[(size_t)(row + 8) * ldc + col]) =
                make_float2(acc[mt][nt][2], acc[mt][nt][3]);
        }
    }
}

// ---------------------------------------------------------------------------
// Elementwise: gates + cache roll/scatter + depthwise conv + C-gate -> y fp16
// ---------------------------------------------------------------------------
__global__ __launch_bounds__(256) void k_elem(
    const float* __restrict__ conv_cache, const float* __restrict__ conv_w,
    const int* __restrict__ pos_ids, float* __restrict__ out_state)
{
    const int idx = blockIdx.x * 256 + threadIdx.x;   // b*2048 + d
    const int b = idx >> 11, d = idx & 2047;

    const float Bg = g_bcx[(size_t)b * 6144 + d];
    const float Cg = g_bcx[(size_t)b * 6144 + 2048 + d];
    const float xg = g_bcx[(size_t)b * 6144 + 4096 + d];
    const float Bx = Bg * xg;

    int pos = pos_ids[0];
    pos = min(max(pos, 0), 3);

    const float4 cc = *reinterpret_cast<const float4*>(conv_cache + (size_t)idx * 4);
    float st[4] = {cc.y, cc.z, cc.w, cc.x};
    st[pos] = Bx;

    const float4 cw = *reinterpret_cast<const float4*>(conv_w + (size_t)d * 4);
    const float co = st[0] * cw.x + st[1] * cw.y + st[2] * cw.z + st[3] * cw.w;

    g_yh[idx] = __float2half(Cg * co);
    *reinterpret_cast<float4*>(out_state + (size_t)idx * 4) =
        make_float4(st[0], st[1], st[2], st[3]);
}

// split-K reduce: out = p0 + p1
__global__ __launch_bounds__(256) void k_red(float* __restrict__ out)
{
    const int i = blockIdx.x * 256 + threadIdx.x;     // float4 index
    const float4 a = reinterpret_cast<const float4*>(g_p)[i];
    const float4 b = reinterpret_cast<const float4*>(g_p + Bm * Dm)[i];
    reinterpret_cast<float4*>(out)[i] =
        make_float4(a.x + b.x, a.y + b.y, a.z + b.z, a.w + b.w);
}

// ---------------------------------------------------------------------------
typedef CUresult (*encode_t)(
    CUtensorMap*, CUtensorMapDataType, cuuint32_t, void*,
    const cuuint64_t*, const cuuint64_t*, const cuuint32_t*, const cuuint32_t*,
    CUtensorMapInterleave, CUtensorMapSwizzle, CUtensorMapL2promotion,
    CUtensorMapFloatOOBfill);

static void make_tm(encode_t enc, CUtensorMap* tm, const void* ptr,
                    uint64_t inner, uint64_t outer,
                    uint32_t box_inner, uint32_t box_outer) {
    cuuint64_t dims[2]    = {inner, outer};
    cuuint64_t strides[1] = {inner * 2};   // bytes between outer rows
    cuuint32_t box[2]     = {box_inner, box_outer};
    cuuint32_t es[2]      = {1, 1};
    enc(tm, CU_TENSOR_MAP_DATA_TYPE_UINT16, 2, (void*)ptr, dims, strides, box,
        es, CU_TENSOR_MAP_INTERLEAVE_NONE, CU_TENSOR_MAP_SWIZZLE_128B,
        CU_TENSOR_MAP_L2_PROMOTION_L2_128B, CU_TENSOR_MAP_FLOAT_OOB_FILL_NONE);
}

extern "C" void kernel_launch(void* const* d_in, const int* in_sizes, int n_in,
                              void* d_out, int out_size) {
    const float* x          = (const float*)d_in[0];
    const float* conv_cache = (const float*)d_in[1];
    const float* w1         = (const float*)d_in[2];
    const float* w2         = (const float*)d_in[3];
    const float* conv_w     = (const float*)d_in[4];
    const int*   pos_ids    = (const int*)d_in[5];

    float* out       = (float*)d_out;            // [B,1,D]
    float* out_state = out + (size_t)Bm * Dm;    // [B,D,K]

    float *bcx = nullptr, *pp = nullptr;
    __half *w1h = nullptr, *w2h = nullptr, *xh = nullptr, *yh = nullptr;
    cudaGetSymbolAddress((void**)&bcx, g_bcx);
    cudaGetSymbolAddress((void**)&pp, g_p);
    cudaGetSymbolAddress((void**)&w1h, g_w1h);
    cudaGetSymbolAddress((void**)&w2h, g_w2h);
    cudaGetSymbolAddress((void**)&xh, g_xh);
    cudaGetSymbolAddress((void**)&yh, g_yh);

    // tensor maps (host-side; runs at capture time, not in the graph)
    void* fp = nullptr;
    cudaDriverEntryPointQueryResult qr;
    cudaGetDriverEntryPoint("cuTensorMapEncodeTiled", &fp, cudaEnableDefault, &qr);
    encode_t enc = (encode_t)fp;

    CUtensorMap tmX, tmW1, tmY, tmW2;
    make_tm(enc, &tmX,  xh,  Dm, Bm,      64, 128);   // A of GEMM1
    make_tm(enc, &tmW1, w1h, Dm, 3 * Dm,  64, 96);    // B of GEMM1
    make_tm(enc, &tmY,  yh,  Dm, Bm,      64, 64);    // A of GEMM2
    make_tm(enc, &tmW2, w2h, Dm, Dm,      64, 128);   // B of GEMM2

    // converts
    k_cvt_all<<<2048, 256>>>((const float4*)w1, (const float4*)w2,
                             (const float4*)x,
                             (uint2*)w1h, (uint2*)w2h, (uint2*)xh);

    // GEMM1: 128x96 tile, 4 warps of 64x48, 5 stages; grid 64x2 = 128 CTAs
    constexpr int SMEM1 = 2048 + 5 * (128 + 96) * 128;   // 145408 B
    // GEMM2: 64x128 tile, 4 warps of 64x32, 5 stages, split-K=2; 16x4x2 = 128
    constexpr int SMEM2 = 2048 + 5 * (64 + 128) * 128;   // 124928 B
    cudaFuncSetAttribute((const void*)k_tma<128, 96, 64, 48, 5, 1, false>,
                         cudaFuncAttributeMaxDynamicSharedMemorySize, SMEM1);
    cudaFuncSetAttribute((const void*)k_tma<64, 128, 64, 32, 5, 2, true>,
                         cudaFuncAttributeMaxDynamicSharedMemorySize, SMEM2);

    // GEMM1: BCx[256, 6144] = x @ w1^T
    k_tma<128, 96, 64, 48, 5, 1, false>
        <<<dim3(3 * Dm / 96, Bm / 128), 128, SMEM1>>>(tmX, tmW1, bcx, 3 * Dm);

    // gating + conv + state scatter
    k_elem<<<(Bm * Dm) / 256, 256>>>(conv_cache, conv_w, pos_ids, out_state);

    // GEMM2 partials: p[z] = y @ w2^T over K-half z
    k_tma<64, 128, 64, 32, 5, 2, true>
        <<<dim3(Dm / 128, Bm / 64, 2), 128, SMEM2>>>(tmY, tmW2, pp, Dm);

    // out = p0 + p1
    k_red<<<(Bm * Dm / 4) / 256, 256>>>(out);
}

// round 14
// speedup vs baseline: 1.3623x; 1.1452x over previous
#include <cuda_runtime.h>
#include <cuda_fp16.h>
#include <cuda.h>
#include <cstdint>

#define Dm 2048
#define Bm 256

// scratch (no cudaMalloc allowed)
__device__ float g_bcx[Bm * 3 * Dm];                 // GEMM1 out [256, 6144] fp32
__device__ __align__(16) __half g_w2h[Dm * Dm];      // w2 fp16 [2048, 2048]
__device__ __align__(16) __half g_xh[Bm * Dm];       // x  fp16 [256, 2048]
__device__ __align__(16) __half g_yh[Bm * Dm];       // y  fp16 [256, 2048]
__device__ __align__(16) float  g_p[2 * Bm * Dm];    // GEMM2 split-K partials

__device__ __forceinline__ uint32_t pack_h2(float lo, float hi) {
    uint32_t r;
    asm("cvt.rn.f16x2.f32 %0, %1, %2;" : "=r"(r) : "f"(hi), "f"(lo));
    return r;
}
__device__ __forceinline__ void mma16(float* d, const uint32_t* a, const uint32_t* b) {
    asm volatile(
        "mma.sync.aligned.m16n8k16.row.col.f32.f16.f16.f32 "
        "{%0,%1,%2,%3}, {%4,%5,%6,%7}, {%8,%9}, {%0,%1,%2,%3};"
        : "+f"(d[0]), "+f"(d[1]), "+f"(d[2]), "+f"(d[3])
        : "r"(a[0]), "r"(a[1]), "r"(a[2]), "r"(a[3]), "r"(b[0]), "r"(b[1]));
}
__device__ __forceinline__ void ldsm4(uint32_t* r, uint32_t addr) {
    asm volatile("ldmatrix.sync.aligned.m8n8.x4.shared.b16 {%0,%1,%2,%3}, [%4];"
                 : "=r"(r[0]), "=r"(r[1]), "=r"(r[2]), "=r"(r[3]) : "r"(addr));
}
__device__ __forceinline__ float2 lds64(uint32_t addr) {
    float2 v;
    asm volatile("ld.shared.v2.f32 {%0,%1}, [%2];"
                 : "=f"(v.x), "=f"(v.y) : "r"(addr));
    return v;
}
__device__ __forceinline__ void mbar_init(uint32_t addr, uint32_t cnt) {
    asm volatile("mbarrier.init.shared.b64 [%0], %1;" :: "r"(addr), "r"(cnt) : "memory");
}
__device__ __forceinline__ void mbar_expect_tx(uint32_t addr, uint32_t bytes) {
    asm volatile("mbarrier.arrive.expect_tx.shared.b64 _, [%0], %1;"
                 :: "r"(addr), "r"(bytes) : "memory");
}
__device__ __forceinline__ void mbar_wait(uint32_t addr, uint32_t parity) {
    asm volatile(
        "{\n\t.reg .pred P1;\n\t"
        "WL%=:\n\t"
        "mbarrier.try_wait.parity.shared.b64 P1, [%0], %1;\n\t"
        "@P1 bra.uni WD%=;\n\t"
        "bra.uni WL%=;\n\t"
        "WD%=:\n\t}"
        :: "r"(addr), "r"(parity) : "memory");
}
__device__ __forceinline__ void tma2d(uint32_t saddr, const void* tm,
                                      int32_t x, int32_t y, uint32_t mbar) {
    asm volatile(
        "cp.async.bulk.tensor.2d.shared::cta.global.tile.mbarrier::complete_tx::bytes "
        "[%0], [%1, {%2, %3}], [%4];"
        :: "r"(saddr), "l"(tm), "r"(x), "r"(y), "r"(mbar) : "memory");
}

// ---------------------------------------------------------------------------
// fp32 -> fp16 convert for w2 | x only (w1 consumed as fp32 by GEMM1)
// ---------------------------------------------------------------------------
__global__ __launch_bounds__(256) void k_cvt(
    const float4* __restrict__ w2, const float4* __restrict__ x,
    uint2* __restrict__ w2h, uint2* __restrict__ xh)
{
    constexpr int N2 = Dm * Dm / 4;
    constexpr int N3 = Bm * Dm / 4;
    const int stride = gridDim.x * 256;
    for (int i = blockIdx.x * 256 + threadIdx.x; i < N2 + N3; i += stride) {
        const float4* s; uint2* d; int j;
        if (i < N2) { s = w2; d = w2h; j = i; }
        else        { s = x;  d = xh;  j = i - N2; }
        float4 v = s[j];
        d[j] = make_uint2(pack_h2(v.x, v.y), pack_h2(v.z, v.w));
    }
}

// ---------------------------------------------------------------------------
// GEMM1: BCx[256,6144] = x[256,2048](fp16) @ w1[6144,2048](fp32, on-the-fly)^T
// Tile 128x96, 4 warps of 64x48, BK=64, 4-stage TMA pipeline.
// A: fp16 SW128 rows (128B), ldmatrix.  B: w1 bytes viewed as uint16
// [4096 x 6144] via TMA (same bytes as fp32), two 128B k-halves per stage;
// frags via lds.64 + cvt.rn.f16x2 (swizzle xor is per-lane constant g<<4).
// ---------------------------------------------------------------------------
__global__ __launch_bounds__(128, 1) void k_g1(
    const __grid_constant__ CUtensorMap tmA,   // xh  fp16 [2048 x 256]
    const __grid_constant__ CUtensorMap tmB,   // w1 bytes as u16 [4096 x 6144]
    float* __restrict__ C)                     // ldc = 6144
{
    constexpr int STAGES = 4;
    constexpr int ABYT = 128 * 128;             // A stage: 128 rows x 128B
    constexpr int BBYT = 96 * 128;              // one 32-float k-half of B
    constexpr int STGB = ABYT + 2 * BBYT;       // 40960
    constexpr int NSTG = Dm / 64;               // 32

    extern __shared__ uint8_t smem[];
    const int tid = threadIdx.x;
    const int wid = tid >> 5, lane = tid & 31;
    const int g = lane >> 2, c = lane & 3;
    const int wm = (wid >> 1) * 64, wn = (wid & 1) * 48;
    const int mBase = blockIdx.y * 128, nBase = blockIdx.x * 96;

    uint32_t sraw = (uint32_t)__cvta_generic_to_shared(smem);
    const uint32_t mb0 = sraw;
    uint32_t sb0 = (sraw + 1023u) & ~1023u;
    const uint32_t sbA = (sb0 < sraw + 8u * STAGES) ? sb0 + 1024u : sb0;

    if (tid == 0)
        for (int i = 0; i < STAGES; i++) mbar_init(mb0 + i * 8, 1);
    __syncthreads();

    const int lr = lane & 7, mat = lane >> 3;
    const uint32_t axor = (uint32_t)lr << 4;
    const uint32_t acb = (uint32_t)(mat >> 1) * 16;
    uint32_t arow[4];
    #pragma unroll
    for (int mt = 0; mt < 4; mt++)
        arow[mt] = (uint32_t)(wm + mt * 16 + (mat & 1) * 8 + lr) * 128;
    const uint32_t bxor = (uint32_t)g << 4;     // row%8 == g for B-frag rows
    const uint32_t brow0 = (uint32_t)(wn + g) * 128;

    float acc[4][6][4] = {};

    auto issue = [&](int slot, int k0) {        // k0 in floats
        if (tid == 0) {
            const uint32_t bar = mb0 + slot * 8;
            mbar_expect_tx(bar, STGB);
            const uint32_t sb = sbA + slot * STGB;
            tma2d(sb, &tmA, k0, mBase, bar);                     // fp16 coords
            tma2d(sb + ABYT,        &tmB, 2 * k0,      nBase, bar);  // u16 view
            tma2d(sb + ABYT + BBYT, &tmB, 2 * k0 + 64, nBase, bar);
        }
    };

    #pragma unroll
    for (int s = 0; s < STAGES - 1; s++) issue(s, s * 64);

    int slot = 0, ph = 0, islot = STAGES - 1;
    for (int s = 0; s < NSTG; s++) {
        mbar_wait(mb0 + slot * 8, ph);
        __syncthreads();

        if (s + STAGES - 1 < NSTG) issue(islot, (s + STAGES - 1) * 64);
        islot = (islot + 1 == STAGES) ? 0 : islot + 1;

        const uint32_t sb = sbA + slot * STGB;
        #pragma unroll
        for (int step = 0; step < 4; step++) {
            const uint32_t kb = step * 32;               // A: 16 halves = 32B
            uint32_t af[4][4], bf[6][2];
            #pragma unroll
            for (int mt = 0; mt < 4; mt++)
                ldsm4(af[mt], sb + arow[mt] + ((acb + kb) ^ axor));

            const uint32_t bpart = sb + ABYT + (step >> 1) * BBYT;
            const uint32_t fb = (step & 1) * 64;         // byte base in 128B row
            #pragma unroll
            for (int nt = 0; nt < 6; nt++) {
                const uint32_t ba = bpart + brow0 + nt * 1024;   // 8 rows*128B
                float2 v0 = lds64(ba + ((fb + 8 * c) ^ bxor));
                float2 v1 = lds64(ba + ((fb + 8 * c + 32) ^ bxor));
                bf[nt][0] = pack_h2(v0.x, v0.y);
                bf[nt][1] = pack_h2(v1.x, v1.y);
            }
            #pragma unroll
            for (int mt = 0; mt < 4; mt++)
                #pragma unroll
                for (int nt = 0; nt < 6; nt++)
                    mma16(acc[mt][nt], af[mt], bf[nt]);
        }
        slot++; if (slot == STAGES) { slot = 0; ph ^= 1; }
    }

    #pragma unroll
    for (int mt = 0; mt < 4; mt++) {
        const int row = mBase + wm + mt * 16 + g;
        #pragma unroll
        for (int nt = 0; nt < 6; nt++) {
            const int col = nBase + wn + nt * 8 + 2 * c;
            *reinterpret_cast<float2*>(&C[(size_t)row * 6144 + col]) =
                make_float2(acc[mt][nt][0], acc[mt][nt][1]);
            *reinterpret_cast<float2*>(&C[(size_t)(row + 8) * 6144 + col]) =
                make_float2(acc[mt][nt][2], acc[mt][nt][3]);
        }
    }
}

// ---------------------------------------------------------------------------
// GEMM2 (fp16 TMA, 8 warps): p[z] = y @ w2^T over K-half z. Tile 64x128,
// warp 32x32 (grid 2x4), 4 stages, split-K=2.
// ---------------------------------------------------------------------------
__global__ __launch_bounds__(256, 1) void k_g2(
    const __grid_constant__ CUtensorMap tmA,   // yh  fp16 [2048 x 256]
    const __grid_constant__ CUtensorMap tmB,   // w2h fp16 [2048 x 2048]
    float* __restrict__ C)                     // g_p, ldc = 2048
{
    constexpr int BM = 64, BN = 128, STAGES = 4;
    constexpr int STGB = (BM + BN) * 128;       // 24576
    constexpr int NSTG = (Dm / 2) / 64;         // 16

    extern __shared__ uint8_t smem[];
    const int tid = threadIdx.x;
    const int wid = tid >> 5, lane = tid & 31;
    const int g = lane >> 2, c = lane & 3;
    const int wm = (wid >> 2) * 32, wn = (wid & 3) * 32;
    const int mBase = blockIdx.y * BM, nBase = blockIdx.x * BN;
    const int kBase = blockIdx.z * (Dm / 2);

    uint32_t sraw = (uint32_t)__cvta_generic_to_shared(smem);
    const uint32_t mb0 = sraw;
    uint32_t sb0 = (sraw + 1023u) & ~1023u;
    const uint32_t sbA = (sb0 < sraw + 8u * STAGES) ? sb0 + 1024u : sb0;

    if (tid == 0)
        for (int i = 0; i < STAGES; i++) mbar_init(mb0 + i * 8, 1);
    __syncthreads();

    const int lr = lane & 7, mat = lane >> 3;
    const uint32_t axor = (uint32_t)lr << 4;
    const uint32_t acb = (uint32_t)(mat >> 1) * 16;
    uint32_t arow[2];
    #pragma unroll
    for (int mt = 0; mt < 2; mt++)
        arow[mt] = (uint32_t)(wm + mt * 16 + (mat & 1) * 8 + lr) * 128;
    const uint32_t bcb = (uint32_t)(mat & 1) * 16;
    uint32_t brow[2];
    #pragma unroll
    for (int p = 0; p < 2; p++)
        brow[p] = (uint32_t)(BM + wn + p * 16 + (mat >> 1) * 8 + lr) * 128;

    float acc[2][4][4] = {};

    auto issue = [&](int slot, int k0) {
        if (tid == 0) {
            const uint32_t bar = mb0 + slot * 8;
            mbar_expect_tx(bar, STGB);
            tma2d(sbA + slot * STGB, &tmA, k0, mBase, bar);
            tma2d(sbA + slot * STGB + BM * 128, &tmB, k0, nBase, bar);
        }
    };

    #pragma unroll
    for (int s = 0; s < STAGES - 1; s++) issue(s, kBase + s * 64);

    int slot = 0, ph = 0, islot = STAGES - 1;
    for (int s = 0; s < NSTG; s++) {
        mbar_wait(mb0 + slot * 8, ph);
        __syncthreads();

        if (s + STAGES - 1 < NSTG) issue(islot, kBase + (s + STAGES - 1) * 64);
        islot = (islot + 1 == STAGES) ? 0 : islot + 1;

        const uint32_t sb = sbA + slot * STGB;
        #pragma unroll
        for (int step = 0; step < 4; step++) {
            const uint32_t kb = step * 32;
            uint32_t af[2][4], bf[4][2];
            #pragma unroll
            for (int mt = 0; mt < 2; mt++)
                ldsm4(af[mt], sb + arow[mt] + ((acb + kb) ^ axor));
            #pragma unroll
            for (int p = 0; p < 2; p++) {
                uint32_t r[4];
                ldsm4(r, sb + brow[p] + ((bcb + kb) ^ axor));
                bf[2 * p][0] = r[0]; bf[2 * p][1] = r[1];
                bf[2 * p + 1][0] = r[2]; bf[2 * p + 1][1] = r[3];
            }
            #pragma unroll
            for (int mt = 0; mt < 2; mt++)
                #pragma unroll
                for (int nt = 0; nt < 4; nt++)
                    mma16(acc[mt][nt], af[mt], bf[nt]);
        }
        slot++; if (slot == STAGES) { slot = 0; ph ^= 1; }
    }

    const int rOff = (int)blockIdx.z * Bm;
    #pragma unroll
    for (int mt = 0; mt < 2; mt++) {
        const int row = rOff + mBase + wm + mt * 16 + g;
        #pragma unroll
        for (int nt = 0; nt < 4; nt++) {
            const int col = nBase + wn + nt * 8 + 2 * c;
            *reinterpret_cast<float2*>(&C[(size_t)row * Dm + col]) =
                make_float2(acc[mt][nt][0], acc[mt][nt][1]);
            *reinterpret_cast<float2*>(&C[(size_t)(row + 8) * Dm + col]) =
                make_float2(acc[mt][nt][2], acc[mt][nt][3]);
        }
    }
}

// ---------------------------------------------------------------------------
// Elementwise: gates + cache roll/scatter + depthwise conv + C-gate -> y fp16
// ---------------------------------------------------------------------------
__global__ __launch_bounds__(256) void k_elem(
    const float* __restrict__ conv_cache, const float* __restrict__ conv_w,
    const int* __restrict__ pos_ids, float* __restrict__ out_state)
{
    const int idx = blockIdx.x * 256 + threadIdx.x;   // b*2048 + d
    const int b = idx >> 11, d = idx & 2047;

    const float Bg = g_bcx[(size_t)b * 6144 + d];
    const float Cg = g_bcx[(size_t)b * 6144 + 2048 + d];
    const float xg = g_bcx[(size_t)b * 6144 + 4096 + d];
    const float Bx = Bg * xg;

    int pos = pos_ids[0];
    pos = min(max(pos, 0), 3);

    const float4 cc = *reinterpret_cast<const float4*>(conv_cache + (size_t)idx * 4);
    float st[4] = {cc.y, cc.z, cc.w, cc.x};
    st[pos] = Bx;

    const float4 cw = *reinterpret_cast<const float4*>(conv_w + (size_t)d * 4);
    const float co = st[0] * cw.x + st[1] * cw.y + st[2] * cw.z + st[3] * cw.w;

    g_yh[idx] = __float2half(Cg * co);
    *reinterpret_cast<float4*>(out_state + (size_t)idx * 4) =
        make_float4(st[0], st[1], st[2], st[3]);
}

// split-K reduce: out = p0 + p1
__global__ __launch_bounds__(256) void k_red(float* __restrict__ out)
{
    const int i = blockIdx.x * 256 + threadIdx.x;
    const float4 a = reinterpret_cast<const float4*>(g_p)[i];
    const float4 b = reinterpret_cast<const float4*>(g_p + Bm * Dm)[i];
    reinterpret_cast<float4*>(out)[i] =
        make_float4(a.x + b.x, a.y + b.y, a.z + b.z, a.w + b.w);
}

// ---------------------------------------------------------------------------
typedef CUresult (*encode_t)(
    CUtensorMap*, CUtensorMapDataType, cuuint32_t, void*,
    const cuuint64_t*, const cuuint64_t*, const cuuint32_t*, const cuuint32_t*,
    CUtensorMapInterleave, CUtensorMapSwizzle, CUtensorMapL2promotion,
    CUtensorMapFloatOOBfill);

static void make_tm(encode_t enc, CUtensorMap* tm, const void* ptr,
                    uint64_t inner, uint64_t outer,
                    uint32_t box_inner, uint32_t box_outer) {
    cuuint64_t dims[2]    = {inner, outer};
    cuuint64_t strides[1] = {inner * 2};   // uint16 elements everywhere
    cuuint32_t box[2]     = {box_inner, box_outer};
    cuuint32_t es[2]      = {1, 1};
    enc(tm, CU_TENSOR_MAP_DATA_TYPE_UINT16, 2, (void*)ptr, dims, strides, box,
        es, CU_TENSOR_MAP_INTERLEAVE_NONE, CU_TENSOR_MAP_SWIZZLE_128B,
        CU_TENSOR_MAP_L2_PROMOTION_L2_128B, CU_TENSOR_MAP_FLOAT_OOB_FILL_NONE);
}

extern "C" void kernel_launch(void* const* d_in, const int* in_sizes, int n_in,
                              void* d_out, int out_size) {
    const float* x          = (const float*)d_in[0];
    const float* conv_cache = (const float*)d_in[1];
    const float* w1         = (const float*)d_in[2];
    const float* w2         = (const float*)d_in[3];
    const float* conv_w     = (const float*)d_in[4];
    const int*   pos_ids    = (const int*)d_in[5];

    float* out       = (float*)d_out;            // [B,1,D]
    float* out_state = out + (size_t)Bm * Dm;    // [B,D,K]

    float *bcx = nullptr, *pp = nullptr;
    __half *w2h = nullptr, *xh = nullptr, *yh = nullptr;
    cudaGetSymbolAddress((void**)&bcx, g_bcx);
    cudaGetSymbolAddress((void**)&pp, g_p);
    cudaGetSymbolAddress((void**)&w2h, g_w2h);
    cudaGetSymbolAddress((void**)&xh, g_xh);
    cudaGetSymbolAddress((void**)&yh, g_yh);

    void* fp = nullptr;
    cudaDriverEntryPointQueryResult qr;
    cudaGetDriverEntryPoint("cuTensorMapEncodeTiled", &fp, cudaEnableDefault, &qr);
    encode_t enc = (encode_t)fp;

    // All tensor maps use UINT16 element type (byte view; TMA is type-agnostic).
    CUtensorMap tmX, tmW1, tmY, tmW2;
    make_tm(enc, &tmX,  xh,  Dm,     Bm,     64, 128);  // fp16 x
    make_tm(enc, &tmW1, w1,  2 * Dm, 3 * Dm, 64, 96);   // fp32 w1 as u16 bytes
    make_tm(enc, &tmY,  yh,  Dm,     Bm,     64, 64);   // fp16 y
    make_tm(enc, &tmW2, w2h, Dm,     Dm,     64, 128);  // fp16 w2

    // converts (w2 + x only)
    k_cvt<<<1024, 256>>>((const float4*)w2, (const float4*)x,
                         (uint2*)w2h, (uint2*)xh);

    constexpr int SMEM1 = 2048 + 4 * 40960;   // 165888
    constexpr int SMEM2 = 2048 + 4 * 24576;   // 100352
    cudaFuncSetAttribute((const void*)k_g1,
                         cudaFuncAttributeMaxDynamicSharedMemorySize, SMEM1);
    cudaFuncSetAttribute((const void*)k_g2,
                         cudaFuncAttributeMaxDynamicSharedMemorySize, SMEM2);

    // GEMM1: BCx = x @ w1^T  (w1 fp32 on the fly); grid 64x2 = 128 CTAs
    k_g1<<<dim3(3 * Dm / 96, Bm / 128), 128, SMEM1>>>(tmX, tmW1, bcx);

    // gating + conv + state scatter
    k_elem<<<(Bm * Dm) / 256, 256>>>(conv_cache, conv_w, pos_ids, out_state);

    // GEMM2 partials (split-K=2); grid 16x4x2 = 128 CTAs
    k_g2<<<dim3(Dm / 128, Bm / 64, 2), 256, SMEM2>>>(tmY, tmW2, pp);

    // out = p0 + p1
    k_red<<<(Bm * Dm / 4) / 256, 256>>>(out);
}